// round 1
// baseline (speedup 1.0000x reference)
#include <cuda_runtime.h>
#include <math.h>

// SDF2: mesh -> signed-distance-ish voxel grid.
//   faces:    int32  (1, 2048, 3)   -> 6144 elems
//   vertices: fp32   (1, 1026, 3)   -> 3078 elems
//   grid_size: 32 (scalar input; G hardcoded, out_size confirms 32^3)
// out: fp32 (1, 32, 32, 32) = 32768, pts = meshgrid ij of (i+0.5)/32.

#define G_DIM   32
#define N_PTS   (G_DIM * G_DIM * G_DIM)
#define N_FACES 2048
#define EPSF    1e-12f

#define THREADS 224
#define BLOCKS  148
#define SMEM_BYTES (3 * N_FACES * (int)sizeof(float4))

__global__ void __launch_bounds__(THREADS, 1)
sdf_kernel(const int* __restrict__ faces,
           const float* __restrict__ verts,
           float* __restrict__ out)
{
    extern __shared__ float4 tri[];  // [3*N_FACES]: a,b,c per face

    // Stage all triangles into smem (gather through L2; ~96KB).
    for (int i = threadIdx.x; i < 3 * N_FACES; i += blockDim.x) {
        int vi = faces[i];
        const float* v = verts + 3 * vi;
        tri[i] = make_float4(v[0], v[1], v[2], 0.0f);
    }
    __syncthreads();

    int p = blockIdx.x * THREADS + threadIdx.x;
    if (p >= N_PTS) return;

    int ix = p >> 10;
    int iy = (p >> 5) & 31;
    int iz = p & 31;
    const float inv_g = 1.0f / (float)G_DIM;
    float px = ((float)ix + 0.5f) * inv_g;
    float py = ((float)iy + 0.5f) * inv_g;
    float pz = ((float)iz + 0.5f) * inv_g;

    float md2 = INFINITY;
    int par = 0;

    #pragma unroll 2
    for (int f = 0; f < N_FACES; ++f) {
        float4 A  = tri[3 * f + 0];
        float4 Bv = tri[3 * f + 1];
        float4 Cv = tri[3 * f + 2];

        // ---- closest-point-on-triangle (Ericson), reference override order ----
        float abx = Bv.x - A.x, aby = Bv.y - A.y, abz = Bv.z - A.z;
        float acx = Cv.x - A.x, acy = Cv.y - A.y, acz = Cv.z - A.z;

        float apx = px - A.x,  apy = py - A.y,  apz = pz - A.z;
        float d1 = abx * apx + aby * apy + abz * apz;
        float d2 = acx * apx + acy * apy + acz * apz;

        float bpx = px - Bv.x, bpy = py - Bv.y, bpz = pz - Bv.z;
        float d3 = abx * bpx + aby * bpy + abz * bpz;
        float d4 = acx * bpx + acy * bpy + acz * bpz;

        float cpx = px - Cv.x, cpy = py - Cv.y, cpz = pz - Cv.z;
        float d5 = abx * cpx + aby * cpy + abz * cpz;
        float d6 = acx * cpx + acy * cpy + acz * cpz;

        float va = d3 * d6 - d5 * d4;
        float vb = d5 * d2 - d1 * d6;
        float vc = d1 * d4 - d3 * d2;

        // interior (base case)
        float denom = va + vb + vc;
        denom = (fabsf(denom) < EPSF) ? EPSF : denom;
        float invden = __fdividef(1.0f, denom);
        float vi_ = vb * invden;
        float wi_ = vc * invden;
        float qx = A.x + vi_ * abx + wi_ * acx;
        float qy = A.y + vi_ * aby + wi_ * acy;
        float qz = A.z + vi_ * abz + wi_ * acz;

        // BC edge
        float d43 = d4 - d3, d56 = d5 - d6;
        {
            float t = __fdividef(d43, fmaxf(d43 + d56, EPSF));
            bool c_bc = (va <= 0.0f) & (d43 >= 0.0f) & (d56 >= 0.0f);
            if (c_bc) {
                qx = Bv.x + t * (Cv.x - Bv.x);
                qy = Bv.y + t * (Cv.y - Bv.y);
                qz = Bv.z + t * (Cv.z - Bv.z);
            }
        }
        // AC edge
        {
            float t = __fdividef(d2, fmaxf(d2 - d6, EPSF));
            bool c_ac = (vb <= 0.0f) & (d2 >= 0.0f) & (d6 <= 0.0f);
            if (c_ac) {
                qx = A.x + t * acx;
                qy = A.y + t * acy;
                qz = A.z + t * acz;
            }
        }
        // AB edge
        {
            float t = __fdividef(d1, fmaxf(d1 - d3, EPSF));
            bool c_ab = (vc <= 0.0f) & (d1 >= 0.0f) & (d3 <= 0.0f);
            if (c_ab) {
                qx = A.x + t * abx;
                qy = A.y + t * aby;
                qz = A.z + t * abz;
            }
        }
        // vertex regions (highest priority = last override)
        if ((d6 >= 0.0f) & (d5 <= d6)) { qx = Cv.x; qy = Cv.y; qz = Cv.z; }
        if ((d3 >= 0.0f) & (d4 <= d3)) { qx = Bv.x; qy = Bv.y; qz = Bv.z; }
        if ((d1 <= 0.0f) & (d2 <= 0.0f)) { qx = A.x; qy = A.y; qz = A.z; }

        float dx = px - qx, dy = py - qy, dz = pz - qz;
        float dd = dx * dx + dy * dy + dz * dz;
        md2 = fminf(md2, dd);

        // ---- +z ray crossing (division-free sign tests) ----
        // reference: x0,y0,z0=a; x1,y1,z1=b; x2,y2,z2=c
        float e0 = Bv.y - Cv.y;        // y1 - y2
        float e1 = Cv.x - Bv.x;        // x2 - x1
        float den = e0 * (A.x - Cv.x) + e1 * (A.y - Cv.y);
        float pxc = px - Cv.x, pyc = py - Cv.y;
        float un = e0 * pxc + e1 * pyc;                       // u * den
        float vn = (Cv.y - A.y) * pxc + (A.x - Cv.x) * pyc;   // v * den
        float wn = den - un - vn;                             // w * den
        float zn = un * A.z + vn * Bv.z + wn * Cv.z - pz * den; // (zhit - pz)*den
        bool nondeg = fabsf(den) >= EPSF;
        bool cross = nondeg
                   & (un * den >= 0.0f)
                   & (vn * den >= 0.0f)
                   & (wn * den >= 0.0f)
                   & (zn * den >  0.0f);
        par += cross ? 1 : 0;
    }

    out[p] = (par & 1) ? sqrtf(md2) : 0.0f;
}

extern "C" void kernel_launch(void* const* d_in, const int* in_sizes, int n_in,
                              void* d_out, int out_size)
{
    // Identify inputs by element count (robust to metadata ordering):
    //   faces = 6144 ints, vertices = 3078 floats, grid_size = 1.
    const int* faces = nullptr;
    const float* verts = nullptr;
    for (int i = 0; i < n_in; ++i) {
        if (in_sizes[i] == 3 * N_FACES)      faces = (const int*)d_in[i];
        else if (in_sizes[i] == 3 * 1026)    verts = (const float*)d_in[i];
    }
    if (!faces) faces = (const int*)d_in[0];
    if (!verts) verts = (const float*)d_in[1];

    static bool attr_set = false;
    // cudaFuncSetAttribute is idempotent and not a stream op; safe under capture.
    cudaFuncSetAttribute(sdf_kernel, cudaFuncAttributeMaxDynamicSharedMemorySize,
                         SMEM_BYTES);
    (void)attr_set;

    sdf_kernel<<<BLOCKS, THREADS, SMEM_BYTES>>>(faces, verts, (float*)d_out);
}

// round 3
// speedup vs baseline: 1.8380x; 1.8380x over previous
#include <cuda_runtime.h>
#include <math.h>

// SDF2: mesh -> voxel (inside ? distance : 0) grid.
//   faces: int32 (1,2048,3), vertices: fp32 (1,1026,3), grid 32^3.
// Strategy:
//   - K=4 z-consecutive points per thread (d1,d2 affine in z; 2D ray test z-invariant)
//   - closest point always q = a + s1*ab + s2*ac; cascade selects only (s1,s2);
//     distance via residual vector (cancellation-free, matches reference numerics)
//   - d3..d6 derived from d1,d2 via precomputed |ab|^2, ab.ac, |ac|^2
//   - triangle dim split into 8 chunks -> 256 blocks x 256 thr (2 blocks/SM)
//   - per-chunk partials in __device__ scratch, finalize kernel reduces.

#define G_DIM    32
#define N_PTS    (G_DIM * G_DIM * G_DIM)          // 32768
#define N_FACES  2048
#define N_CHUNK  8
#define TRI_PER_CHUNK (N_FACES / N_CHUNK)         // 256
#define N_GROUPS (N_PTS / 4)                      // 8192
#define EPSF     1e-12f

__device__ float    g_md2s[N_CHUNK * N_PTS];      // per-chunk min squared distance
__device__ unsigned g_pars[N_CHUNK * N_GROUPS];   // per-chunk parity bits (4 pts/word)

__global__ void __launch_bounds__(256, 2)
sdf_main(const int* __restrict__ faces, const float* __restrict__ verts)
{
    __shared__ float4 tri[3 * TRI_PER_CHUNK];     // 12 KB

    const int chunk = blockIdx.y;
    const int tbase3 = chunk * TRI_PER_CHUNK * 3;
    for (int i = threadIdx.x; i < 3 * TRI_PER_CHUNK; i += 256) {
        int vi = faces[tbase3 + i];
        const float* v = verts + 3 * vi;
        tri[i] = make_float4(v[0], v[1], v[2], 0.0f);
    }
    __syncthreads();

    const int g   = blockIdx.x * 256 + threadIdx.x;       // point-group [0,8192)
    const int ix  = g >> 8;
    const int iy  = (g >> 3) & 31;
    const int iz0 = (g & 7) << 2;

    const float inv_g = 1.0f / (float)G_DIM;
    const float px  = ((float)ix  + 0.5f) * inv_g;
    const float py  = ((float)iy  + 0.5f) * inv_g;
    const float pz0 = ((float)iz0 + 0.5f) * inv_g;
    const float dz  = inv_g;

    float md[4] = { INFINITY, INFINITY, INFINITY, INFINITY };
    unsigned par = 0u;

    #pragma unroll 2
    for (int f = 0; f < TRI_PER_CHUNK; ++f) {
        float4 A  = tri[3 * f + 0];
        float4 Bv = tri[3 * f + 1];
        float4 Cv = tri[3 * f + 2];

        // ---- per-triangle z-invariant setup ----
        float abx = Bv.x - A.x, aby = Bv.y - A.y, abz = Bv.z - A.z;
        float acx = Cv.x - A.x, acy = Cv.y - A.y, acz = Cv.z - A.z;

        float qaa = abx * abx + aby * aby + abz * abz;   // |ab|^2
        float qab = abx * acx + aby * acy + abz * acz;   // ab.ac
        float qac = acx * acx + acy * acy + acz * acz;   // |ac|^2

        float apx = px - A.x, apy = py - A.y;
        float apz = pz0 - A.z;
        float d1 = abx * apx + aby * apy + abz * apz;    // ab.ap
        float d2 = acx * apx + acy * apy + acz * apz;    // ac.ap
        const float iab = abz * dz;
        const float iac = acz * dz;

        // ---- ray crossing (z-invariant 2D part) ----
        float cpx2 = px - Cv.x, cpy2 = py - Cv.y;
        float e0  = Bv.y - Cv.y;                          // y1-y2
        float e1  = Cv.x - Bv.x;                          // x2-x1
        float den = e0 * (A.x - Cv.x) + e1 * (A.y - Cv.y);
        float un  = e0 * cpx2 + e1 * cpy2;                        // u*den
        float vn  = (Cv.y - A.y) * cpx2 + (A.x - Cv.x) * cpy2;    // v*den
        float wn  = den - un - vn;                                // w*den
        bool c2d = (fabsf(den) >= EPSF)
                 & (un * den >= 0.0f) & (vn * den >= 0.0f) & (wn * den >= 0.0f);
        float zn = un * A.z + vn * Bv.z + wn * Cv.z - pz0 * den;  // (zhit-pz)*den
        const float dzden = dz * den;

        #pragma unroll
        for (int k = 0; k < 4; ++k) {
            // derived dots:  bp = ap - ab, cp = ap - ac
            float d3 = d1 - qaa;     // ab.bp
            float d4 = d2 - qab;     // ac.bp
            float d5 = d1 - qab;     // ab.cp
            float d6 = d2 - qac;     // ac.cp

            float va = d3 * d6 - d5 * d4;
            float vb = d5 * d2 - d1 * d6;
            float vc = d1 * d4 - d3 * d2;

            // interior barycentric (base case)
            float denom = va + vb + vc;
            denom = (fabsf(denom) < EPSF) ? EPSF : denom;
            float idn = __fdividef(1.0f, denom);
            float s1 = vb * idn;
            float s2 = vc * idn;

            // BC edge: q = b + t(c-b) = a + (1-t)ab + t*ac
            float d43 = d4 - d3, d56 = d5 - d6;
            {
                float t = __fdividef(d43, fmaxf(d43 + d56, EPSF));
                if ((va <= 0.0f) & (d43 >= 0.0f) & (d56 >= 0.0f)) {
                    s1 = 1.0f - t; s2 = t;
                }
            }
            // AC edge: q = a + t*ac
            {
                float t = __fdividef(d2, fmaxf(d2 - d6, EPSF));
                if ((vb <= 0.0f) & (d2 >= 0.0f) & (d6 <= 0.0f)) {
                    s1 = 0.0f; s2 = t;
                }
            }
            // AB edge: q = a + t*ab
            {
                float t = __fdividef(d1, fmaxf(d1 - d3, EPSF));
                if ((vc <= 0.0f) & (d1 >= 0.0f) & (d3 <= 0.0f)) {
                    s1 = t; s2 = 0.0f;
                }
            }
            // vertex regions (highest priority last)
            if ((d6 >= 0.0f) & (d5 <= d6)) { s1 = 0.0f; s2 = 1.0f; }
            if ((d3 >= 0.0f) & (d4 <= d3)) { s1 = 1.0f; s2 = 0.0f; }
            if ((d1 <= 0.0f) & (d2 <= 0.0f)) { s1 = 0.0f; s2 = 0.0f; }

            // residual: r = ap - s1*ab - s2*ac  (cancellation-free distance)
            float rx = apx - s1 * abx - s2 * acx;
            float ry = apy - s1 * aby - s2 * acy;
            float rz = apz - s1 * abz - s2 * acz;
            float dd = rx * rx + ry * ry + rz * rz;
            md[k] = fminf(md[k], dd);

            // ray crossing for this z
            if (c2d & (zn * den > 0.0f)) par ^= (1u << k);

            // advance to next z point
            d1 += iab; d2 += iac;
            apz += dz;
            zn -= dzden;
        }
    }

    const int pbase = ((ix * 32 + iy) * 32 + iz0);        // 4-aligned
    float4 m4 = make_float4(md[0], md[1], md[2], md[3]);
    *reinterpret_cast<float4*>(g_md2s + chunk * N_PTS + pbase) = m4;
    g_pars[chunk * N_GROUPS + g] = par;
}

__global__ void __launch_bounds__(256)
sdf_finalize(float* __restrict__ out)
{
    int p = blockIdx.x * 256 + threadIdx.x;               // [0, 32768)
    float m = INFINITY;
    unsigned par = 0u;
    #pragma unroll
    for (int c = 0; c < N_CHUNK; ++c) {
        m = fminf(m, g_md2s[c * N_PTS + p]);
        par ^= (g_pars[c * N_GROUPS + (p >> 2)] >> (p & 3));
    }
    out[p] = (par & 1u) ? sqrtf(m) : 0.0f;
}

extern "C" void kernel_launch(void* const* d_in, const int* in_sizes, int n_in,
                              void* d_out, int out_size)
{
    const int* faces = nullptr;
    const float* verts = nullptr;
    for (int i = 0; i < n_in; ++i) {
        if (in_sizes[i] == 3 * N_FACES)   faces = (const int*)d_in[i];
        else if (in_sizes[i] == 3 * 1026) verts = (const float*)d_in[i];
    }
    if (!faces) faces = (const int*)d_in[0];
    if (!verts) verts = (const float*)d_in[1];

    dim3 grid(N_GROUPS / 256, N_CHUNK);                   // 32 x 8 = 256 blocks
    sdf_main<<<grid, 256>>>(faces, verts);
    sdf_finalize<<<N_PTS / 256, 256>>>((float*)d_out);
}

// round 4
// speedup vs baseline: 2.9059x; 1.5810x over previous
#include <cuda_runtime.h>
#include <math.h>

// SDF2: mesh -> voxel (inside ? distance : 0) grid.
//   faces: int32 (1,2048,3), vertices: fp32 (1,1026,3), grid 32^3.
// Round-4 strategy:
//   - K=8 z-consecutive points per thread (d1,d2 affine in z)
//   - ALL divide denominators are per-triangle constants (|ab|^2, |ac|^2,
//     |cb|^2, Gram det) -> 4 reciprocals hoisted to setup, t's are single muls
//   - ray crossing fully hoisted: count = clamp(ceil((zhit-pz0)*G),0,8),
//     parity mask (1<<n)-1 applied once per triangle
//   - cascade selects barycentric (s1,s2); distance via residual (no cancellation)
//   - triangles split into 16 chunks -> 256 blocks x 256 thr (2 blocks/SM)
//   - per-chunk partials in __device__ scratch, finalize kernel reduces.

#define G_DIM    32
#define N_PTS    (G_DIM * G_DIM * G_DIM)          // 32768
#define N_FACES  2048
#define N_CHUNK  16
#define TRI_PER_CHUNK (N_FACES / N_CHUNK)         // 128
#define KPT      8
#define N_GROUPS (N_PTS / KPT)                    // 4096
#define EPSF     1e-12f

__device__ float    g_md2s[N_CHUNK * N_PTS];      // per-chunk min squared distance
__device__ unsigned g_pars[N_CHUNK * N_GROUPS];   // per-chunk parity bits (8 pts/word)

__global__ void __launch_bounds__(256, 2)
sdf_main(const int* __restrict__ faces, const float* __restrict__ verts)
{
    __shared__ float4 tri[3 * TRI_PER_CHUNK];     // 6 KB

    const int chunk = blockIdx.y;
    const int tbase3 = chunk * TRI_PER_CHUNK * 3;
    for (int i = threadIdx.x; i < 3 * TRI_PER_CHUNK; i += 256) {
        int vi = faces[tbase3 + i];
        const float* v = verts + 3 * vi;
        tri[i] = make_float4(v[0], v[1], v[2], 0.0f);
    }
    __syncthreads();

    const int g   = blockIdx.x * 256 + threadIdx.x;       // point-group [0,4096)
    const int ix  = g >> 7;
    const int iy  = (g >> 2) & 31;
    const int iz0 = (g & 3) << 3;

    const float inv_g = 1.0f / (float)G_DIM;
    const float px  = ((float)ix  + 0.5f) * inv_g;
    const float py  = ((float)iy  + 0.5f) * inv_g;
    const float pz0 = ((float)iz0 + 0.5f) * inv_g;
    const float dz  = inv_g;

    float md[KPT];
    #pragma unroll
    for (int k = 0; k < KPT; ++k) md[k] = INFINITY;
    unsigned par = 0u;

    for (int f = 0; f < TRI_PER_CHUNK; ++f) {
        float4 A  = tri[3 * f + 0];
        float4 Bv = tri[3 * f + 1];
        float4 Cv = tri[3 * f + 2];

        // ---- per-triangle z-invariant setup ----
        float abx = Bv.x - A.x, aby = Bv.y - A.y, abz = Bv.z - A.z;
        float acx = Cv.x - A.x, acy = Cv.y - A.y, acz = Cv.z - A.z;

        float qaa = abx * abx + aby * aby + abz * abz;   // |ab|^2 (= d1-d3)
        float qab = abx * acx + aby * acy + abz * acz;   // ab.ac
        float qac = acx * acx + acy * acy + acz * acz;   // |ac|^2 (= d2-d6)
        float qbc = qaa - 2.0f * qab + qac;              // |cb|^2 (= d43+d56)
        float gram = qaa * qac - qab * qab;              // = va+vb+vc

        float gden = (fabsf(gram) < EPSF) ? EPSF : gram;
        float idn    = __fdividef(1.0f, gden);
        float inv_ab = __fdividef(1.0f, fmaxf(qaa, EPSF));
        float inv_ac = __fdividef(1.0f, fmaxf(qac, EPSF));
        float inv_bc = __fdividef(1.0f, fmaxf(qbc, EPSF));

        float apx = px - A.x, apy = py - A.y;
        float apz = pz0 - A.z;
        float d1 = abx * apx + aby * apy + abz * apz;    // ab.ap
        float d2 = acx * apx + acy * apy + acz * apz;    // ac.ap
        const float iab = abz * dz;
        const float iac = acz * dz;

        // ---- ray crossing: fully hoisted out of the k loop ----
        {
            float cpx2 = px - Cv.x, cpy2 = py - Cv.y;
            float e0  = Bv.y - Cv.y;                      // y1-y2
            float e1  = Cv.x - Bv.x;                      // x2-x1
            float den = e0 * (A.x - Cv.x) + e1 * (A.y - Cv.y);
            float un  = e0 * cpx2 + e1 * cpy2;                        // u*den
            float vn  = (Cv.y - A.y) * cpx2 + (A.x - Cv.x) * cpy2;    // v*den
            float wn  = den - un - vn;                                // w*den
            bool c2d = (fabsf(den) >= EPSF)
                     & (un * den >= 0.0f) & (vn * den >= 0.0f) & (wn * den >= 0.0f);
            if (c2d) {
                float zhit = __fdividef(un * A.z + vn * Bv.z + wn * Cv.z, den);
                // crossing for k iff zhit > pz0 + k*dz  <=>  k < (zhit-pz0)*G
                float fcnt = (zhit - pz0) * (float)G_DIM;
                int n = (int)ceilf(fminf(fmaxf(fcnt, 0.0f), (float)KPT));
                par ^= (1u << n) - 1u;
            }
        }

        #pragma unroll
        for (int k = 0; k < KPT; ++k) {
            // derived dots: bp = ap - ab, cp = ap - ac
            float d3 = d1 - qaa;     // ab.bp
            float d4 = d2 - qab;     // ac.bp
            float d5 = d1 - qab;     // ab.cp
            float d6 = d2 - qac;     // ac.cp

            float va = d3 * d6 - d5 * d4;
            float vb = d5 * d2 - d1 * d6;
            float vc = d1 * d4 - d3 * d2;

            // interior barycentric (base case)
            float s1 = vb * idn;
            float s2 = vc * idn;

            // BC edge: q = a + (1-t)ab + t*ac
            float d43 = d4 - d3, d56 = d5 - d6;
            {
                float t = d43 * inv_bc;
                if ((va <= 0.0f) & (d43 >= 0.0f) & (d56 >= 0.0f)) {
                    s1 = 1.0f - t; s2 = t;
                }
            }
            // AC edge: q = a + t*ac
            {
                float t = d2 * inv_ac;
                if ((vb <= 0.0f) & (d2 >= 0.0f) & (d6 <= 0.0f)) {
                    s1 = 0.0f; s2 = t;
                }
            }
            // AB edge: q = a + t*ab
            {
                float t = d1 * inv_ab;
                if ((vc <= 0.0f) & (d1 >= 0.0f) & (d3 <= 0.0f)) {
                    s1 = t; s2 = 0.0f;
                }
            }
            // vertex regions (highest priority last)
            if ((d6 >= 0.0f) & (d5 <= d6)) { s1 = 0.0f; s2 = 1.0f; }
            if ((d3 >= 0.0f) & (d4 <= d3)) { s1 = 1.0f; s2 = 0.0f; }
            if ((d1 <= 0.0f) & (d2 <= 0.0f)) { s1 = 0.0f; s2 = 0.0f; }

            // residual: r = ap - s1*ab - s2*ac (cancellation-free distance)
            float rx = apx - s1 * abx - s2 * acx;
            float ry = apy - s1 * aby - s2 * acy;
            float rz = apz - s1 * abz - s2 * acz;
            float dd = rx * rx + ry * ry + rz * rz;
            md[k] = fminf(md[k], dd);

            // advance to next z point
            d1 += iab; d2 += iac; apz += dz;
        }
    }

    const int pbase = ((ix * 32 + iy) * 32 + iz0);        // 8-aligned
    float* dst = g_md2s + chunk * N_PTS + pbase;
    *reinterpret_cast<float4*>(dst)     = make_float4(md[0], md[1], md[2], md[3]);
    *reinterpret_cast<float4*>(dst + 4) = make_float4(md[4], md[5], md[6], md[7]);
    g_pars[chunk * N_GROUPS + g] = par;
}

__global__ void __launch_bounds__(256)
sdf_finalize(float* __restrict__ out)
{
    int p = blockIdx.x * 256 + threadIdx.x;               // [0, 32768)
    float m = INFINITY;
    unsigned par = 0u;
    #pragma unroll
    for (int c = 0; c < N_CHUNK; ++c) {
        m = fminf(m, g_md2s[c * N_PTS + p]);
        par ^= (g_pars[c * N_GROUPS + (p >> 3)] >> (p & 7));
    }
    out[p] = (par & 1u) ? sqrtf(m) : 0.0f;
}

extern "C" void kernel_launch(void* const* d_in, const int* in_sizes, int n_in,
                              void* d_out, int out_size)
{
    const int* faces = nullptr;
    const float* verts = nullptr;
    for (int i = 0; i < n_in; ++i) {
        if (in_sizes[i] == 3 * N_FACES)   faces = (const int*)d_in[i];
        else if (in_sizes[i] == 3 * 1026) verts = (const float*)d_in[i];
    }
    if (!faces) faces = (const int*)d_in[0];
    if (!verts) verts = (const float*)d_in[1];

    dim3 grid(N_GROUPS / 256, N_CHUNK);                   // 16 x 16 = 256 blocks
    sdf_main<<<grid, 256>>>(faces, verts);
    sdf_finalize<<<N_PTS / 256, 256>>>((float*)d_out);
}

// round 5
// speedup vs baseline: 3.3708x; 1.1600x over previous
#include <cuda_runtime.h>
#include <math.h>

// SDF2: mesh -> voxel (inside ? distance : 0) grid.
//   faces: int32 (1,2048,3), vertices: fp32 (1,1026,3), grid 32^3.
// Round-5 strategy:
//   - clamp-min distance: dist = min(clamped AB, AC, BC segment dists),
//     overridden by plane distance h^2/|n|^2 when projection is interior
//     (strict test vb>0 & vc>0 & vb+vc<gram excludes degenerate faces)
//   - h = n.ap is affine in z -> interior dist is 3 ops/k
//   - K=16 z-points/thread; d1,d2,h,apz,bpz all incremental in z
//   - ray crossing hoisted per-triangle (den == nz), parity mask trick
//   - 32 triangle chunks -> 8x32 = 256 blocks x 256 thr (2 blocks/SM)
//   - per-chunk partials in __device__ scratch, finalize kernel reduces.

#define G_DIM    32
#define N_PTS    (G_DIM * G_DIM * G_DIM)          // 32768
#define N_FACES  2048
#define N_CHUNK  32
#define TRI_PER_CHUNK (N_FACES / N_CHUNK)         // 64
#define KPT      16
#define N_GROUPS (N_PTS / KPT)                    // 2048
#define EPSF     1e-12f

__device__ float    g_md2s[N_CHUNK * N_PTS];      // per-chunk min squared distance
__device__ unsigned g_pars[N_CHUNK * N_GROUPS];   // per-chunk parity bits (16 pts/word)

__global__ void __launch_bounds__(256, 2)
sdf_main(const int* __restrict__ faces, const float* __restrict__ verts)
{
    __shared__ float4 tri[3 * TRI_PER_CHUNK];     // 3 KB

    const int chunk = blockIdx.y;
    const int tbase3 = chunk * TRI_PER_CHUNK * 3;
    for (int i = threadIdx.x; i < 3 * TRI_PER_CHUNK; i += 256) {
        int vi = faces[tbase3 + i];
        const float* v = verts + 3 * vi;
        tri[i] = make_float4(v[0], v[1], v[2], 0.0f);
    }
    __syncthreads();

    const int g   = blockIdx.x * 256 + threadIdx.x;       // [0, 2048)
    const int ix  = g >> 6;
    const int iy  = (g >> 1) & 31;
    const int iz0 = (g & 1) << 4;

    const float inv_g = 1.0f / (float)G_DIM;
    const float px  = ((float)ix  + 0.5f) * inv_g;
    const float py  = ((float)iy  + 0.5f) * inv_g;
    const float pz0 = ((float)iz0 + 0.5f) * inv_g;
    const float dz  = inv_g;

    float md[KPT];
    #pragma unroll
    for (int k = 0; k < KPT; ++k) md[k] = INFINITY;
    unsigned par = 0u;

    for (int f = 0; f < TRI_PER_CHUNK; ++f) {
        float4 A  = tri[3 * f + 0];
        float4 Bv = tri[3 * f + 1];
        float4 Cv = tri[3 * f + 2];

        // ---- per-triangle z-invariant setup ----
        float abx = Bv.x - A.x, aby = Bv.y - A.y, abz = Bv.z - A.z;
        float acx = Cv.x - A.x, acy = Cv.y - A.y, acz = Cv.z - A.z;
        float bcx = Cv.x - Bv.x, bcy = Cv.y - Bv.y, bcz = Cv.z - Bv.z;

        float qaa = abx * abx + aby * aby + abz * abz;   // |ab|^2
        float qab = abx * acx + aby * acy + abz * acz;   // ab.ac
        float qac = acx * acx + acy * acy + acz * acz;   // |ac|^2
        float qbc = bcx * bcx + bcy * bcy + bcz * bcz;   // |bc|^2

        float nx = aby * acz - abz * acy;                // n = ab x ac
        float ny = abz * acx - abx * acz;
        float nz = abx * acy - aby * acx;
        float gram = nx * nx + ny * ny + nz * nz;        // |n|^2 >= 0

        float inv_ab = __fdividef(1.0f, fmaxf(qaa,  EPSF));
        float inv_ac = __fdividef(1.0f, fmaxf(qac,  EPSF));
        float inv_bc = __fdividef(1.0f, fmaxf(qbc,  EPSF));
        float inv_n2 = __fdividef(1.0f, fmaxf(gram, EPSF));
        float kbc = qaa - qab;                           // bp.bc = (d2-d1)+kbc

        float apx = px - A.x,  apy = py - A.y;
        float bpx = px - Bv.x, bpy = py - Bv.y;
        float apz = pz0 - A.z;
        float bpz = pz0 - Bv.z;
        float d1 = abx * apx + aby * apy + abz * apz;    // ab.ap
        float d2 = acx * apx + acy * apy + acz * apz;    // ac.ap
        float h  = nx * apx + ny * apy + nz * apz;       // n.ap (affine in z)
        const float iab = abz * dz;
        const float iac = acz * dz;
        const float ihz = nz * dz;

        // ---- ray crossing (den == nz), fully hoisted ----
        {
            float cpx2 = px - Cv.x, cpy2 = py - Cv.y;
            float e0 = Bv.y - Cv.y;                       // y1-y2
            float e1 = Cv.x - Bv.x;                       // x2-x1
            float un = e0 * cpx2 + e1 * cpy2;                         // u*den
            float vn = (Cv.y - A.y) * cpx2 + (A.x - Cv.x) * cpy2;     // v*den
            float wn = nz - un - vn;                                  // w*den
            bool c2d = (fabsf(nz) >= EPSF)
                     & (un * nz >= 0.0f) & (vn * nz >= 0.0f) & (wn * nz >= 0.0f);
            if (c2d) {
                float zhit = __fdividef(un * A.z + vn * Bv.z + wn * Cv.z, nz);
                // crossing for k iff zhit > pz0 + k*dz  <=>  k < (zhit-pz0)*G
                float fcnt = (zhit - pz0) * (float)G_DIM;
                int n = (int)ceilf(fminf(fmaxf(fcnt, 0.0f), (float)KPT));
                par ^= (1u << n) - 1u;
            }
        }

        #pragma unroll
        for (int k = 0; k < KPT; ++k) {
            // AB segment
            float t1 = fminf(fmaxf(d1 * inv_ab, 0.0f), 1.0f);
            float rx = apx - t1 * abx;
            float ry = apy - t1 * aby;
            float rz = apz - t1 * abz;
            float dAB = rx * rx + ry * ry + rz * rz;
            // AC segment
            float t2 = fminf(fmaxf(d2 * inv_ac, 0.0f), 1.0f);
            rx = apx - t2 * acx;
            ry = apy - t2 * acy;
            rz = apz - t2 * acz;
            float dAC = rx * rx + ry * ry + rz * rz;
            // BC segment
            float d43 = (d2 - d1) + kbc;                 // bp.bc
            float t3 = fminf(fmaxf(d43 * inv_bc, 0.0f), 1.0f);
            rx = bpx - t3 * bcx;
            ry = bpy - t3 * bcy;
            rz = bpz - t3 * bcz;
            float dBC = rx * rx + ry * ry + rz * rz;

            float m = fminf(fminf(dAB, dAC), dBC);

            // interior: strict barycentric test (excludes degenerate gram==0)
            float d3 = d1 - qaa, d4 = d2 - qab;
            float d5 = d1 - qab, d6 = d2 - qac;
            float vb = d5 * d2 - d1 * d6;
            float vc = d1 * d4 - d3 * d2;
            if ((vb > 0.0f) & (vc > 0.0f) & (vb + vc < gram))
                m = h * h * inv_n2;                      // plane distance

            md[k] = fminf(md[k], m);

            // advance to next z point
            d1 += iab; d2 += iac; apz += dz; bpz += dz; h += ihz;
        }
    }

    const int pbase = ((ix * 32 + iy) * 32 + iz0);        // 16-aligned
    float* dst = g_md2s + chunk * N_PTS + pbase;
    #pragma unroll
    for (int q = 0; q < KPT / 4; ++q)
        *reinterpret_cast<float4*>(dst + 4 * q) =
            make_float4(md[4*q], md[4*q+1], md[4*q+2], md[4*q+3]);
    g_pars[chunk * N_GROUPS + g] = par;
}

__global__ void __launch_bounds__(256)
sdf_finalize(float* __restrict__ out)
{
    int p = blockIdx.x * 256 + threadIdx.x;               // [0, 32768)
    float m = INFINITY;
    unsigned par = 0u;
    #pragma unroll
    for (int c = 0; c < N_CHUNK; ++c) {
        m = fminf(m, g_md2s[c * N_PTS + p]);
        par ^= (g_pars[c * N_GROUPS + (p >> 4)] >> (p & 15));
    }
    out[p] = (par & 1u) ? sqrtf(m) : 0.0f;
}

extern "C" void kernel_launch(void* const* d_in, const int* in_sizes, int n_in,
                              void* d_out, int out_size)
{
    const int* faces = nullptr;
    const float* verts = nullptr;
    for (int i = 0; i < n_in; ++i) {
        if (in_sizes[i] == 3 * N_FACES)   faces = (const int*)d_in[i];
        else if (in_sizes[i] == 3 * 1026) verts = (const float*)d_in[i];
    }
    if (!faces) faces = (const int*)d_in[0];
    if (!verts) verts = (const float*)d_in[1];

    dim3 grid(N_GROUPS / 256, N_CHUNK);                   // 8 x 32 = 256 blocks
    sdf_main<<<grid, 256>>>(faces, verts);
    sdf_finalize<<<N_PTS / 256, 256>>>((float*)d_out);
}

// round 6
// speedup vs baseline: 4.0549x; 1.2030x over previous
#include <cuda_runtime.h>
#include <math.h>

// SDF2: mesh -> voxel (inside ? distance : 0) grid.
//   faces: int32 (1,2048,3), vertices: fp32 (1,1026,3), grid 32^3.
// Round-6 strategy (on top of round-5 clamp-min formulation):
//   - vb = qac*d1 - qab*d2, vc = qaa*d2 - qab*d1  -> affine in z, incremental
//   - clamps fused into FMUL.SAT via __saturatef
//   - per-triangle constants precomputed once per block into smem (8 float4/tri)
//   - K=16 z-points/thread; d1,d2,h,vb,vc,apz,bpz incremental in z
//   - ray crossing hoisted per-triangle (den == nz), parity mask trick
//   - 32 triangle chunks -> 8x32 = 256 blocks x 256 thr (2 blocks/SM)
//   - per-chunk partials in __device__ scratch, finalize kernel reduces.

#define G_DIM    32
#define N_PTS    (G_DIM * G_DIM * G_DIM)          // 32768
#define N_FACES  2048
#define N_CHUNK  32
#define TRI_PER_CHUNK (N_FACES / N_CHUNK)         // 64
#define KPT      16
#define N_GROUPS (N_PTS / KPT)                    // 2048
#define EPSF     1e-12f

__device__ float    g_md2s[N_CHUNK * N_PTS];      // per-chunk min squared distance
__device__ unsigned g_pars[N_CHUNK * N_GROUPS];   // per-chunk parity bits (16 pts/word)

__global__ void __launch_bounds__(256, 2)
sdf_main(const int* __restrict__ faces, const float* __restrict__ verts)
{
    // 8 float4 per triangle:
    // 0: ab.xyz, inv_ab      1: ac.xyz, inv_ac      2: bc.xyz, inv_bc
    // 3: A.xyz,  kbc         4: B.xyz,  inv_n2      5: C.xyz,  gram
    // 6: n.xyz,  qab         7: qaa, qac, ivb, ivc
    __shared__ float4 tc[8 * TRI_PER_CHUNK];      // 8 KB

    const int chunk = blockIdx.y;

    // ---- staging: one thread per triangle computes all constants ----
    if (threadIdx.x < TRI_PER_CHUNK) {
        const int f = threadIdx.x;
        const int base = (chunk * TRI_PER_CHUNK + f) * 3;
        const float* va = verts + 3 * faces[base + 0];
        const float* vbv = verts + 3 * faces[base + 1];
        const float* vcv = verts + 3 * faces[base + 2];
        float Ax = va[0],  Ay = va[1],  Az = va[2];
        float Bx = vbv[0], By = vbv[1], Bz = vbv[2];
        float Cx = vcv[0], Cy = vcv[1], Cz = vcv[2];

        float abx = Bx - Ax, aby = By - Ay, abz = Bz - Az;
        float acx = Cx - Ax, acy = Cy - Ay, acz = Cz - Az;
        float bcx = Cx - Bx, bcy = Cy - By, bcz = Cz - Bz;

        float qaa = abx * abx + aby * aby + abz * abz;
        float qab = abx * acx + aby * acy + abz * acz;
        float qac = acx * acx + acy * acy + acz * acz;
        float qbc = bcx * bcx + bcy * bcy + bcz * bcz;

        float nx = aby * acz - abz * acy;
        float ny = abz * acx - abx * acz;
        float nz = abx * acy - aby * acx;
        float gram = nx * nx + ny * ny + nz * nz;

        const float dzc = 1.0f / (float)G_DIM;
        float ivb = (qac * abz - qab * acz) * dzc;   // z-step of vb
        float ivc = (qaa * acz - qab * abz) * dzc;   // z-step of vc

        tc[8 * f + 0] = make_float4(abx, aby, abz, __fdividef(1.0f, fmaxf(qaa, EPSF)));
        tc[8 * f + 1] = make_float4(acx, acy, acz, __fdividef(1.0f, fmaxf(qac, EPSF)));
        tc[8 * f + 2] = make_float4(bcx, bcy, bcz, __fdividef(1.0f, fmaxf(qbc, EPSF)));
        tc[8 * f + 3] = make_float4(Ax, Ay, Az, qaa - qab);   // kbc = bp.bc const part
        tc[8 * f + 4] = make_float4(Bx, By, Bz, __fdividef(1.0f, fmaxf(gram, EPSF)));
        tc[8 * f + 5] = make_float4(Cx, Cy, Cz, gram);
        tc[8 * f + 6] = make_float4(nx, ny, nz, qab);
        tc[8 * f + 7] = make_float4(qaa, qac, ivb, ivc);
    }
    __syncthreads();

    const int g   = blockIdx.x * 256 + threadIdx.x;       // [0, 2048)
    const int ix  = g >> 6;
    const int iy  = (g >> 1) & 31;
    const int iz0 = (g & 1) << 4;

    const float inv_g = 1.0f / (float)G_DIM;
    const float px  = ((float)ix  + 0.5f) * inv_g;
    const float py  = ((float)iy  + 0.5f) * inv_g;
    const float pz0 = ((float)iz0 + 0.5f) * inv_g;
    const float dz  = inv_g;

    float md[KPT];
    #pragma unroll
    for (int k = 0; k < KPT; ++k) md[k] = INFINITY;
    unsigned par = 0u;

    for (int f = 0; f < TRI_PER_CHUNK; ++f) {
        const float4 c0 = tc[8 * f + 0];
        const float4 c1 = tc[8 * f + 1];
        const float4 c2 = tc[8 * f + 2];
        const float4 c3 = tc[8 * f + 3];
        const float4 c4 = tc[8 * f + 4];
        const float4 c5 = tc[8 * f + 5];
        const float4 c6 = tc[8 * f + 6];
        const float4 c7 = tc[8 * f + 7];
        const float abx = c0.x, aby = c0.y, abz = c0.z, inv_ab = c0.w;
        const float acx = c1.x, acy = c1.y, acz = c1.z, inv_ac = c1.w;
        const float bcx = c2.x, bcy = c2.y, bcz = c2.z, inv_bc = c2.w;
        const float kbc = c3.w, inv_n2 = c4.w, gram = c5.w;
        const float nx = c6.x, ny = c6.y, nz = c6.z, qab = c6.w;
        const float qaa = c7.x, qac = c7.y, ivb = c7.z, ivc = c7.w;

        // ---- per-thread init (z-invariant parts) ----
        const float apx = px - c3.x, apy = py - c3.y;
        const float bpx = px - c4.x, bpy = py - c4.y;
        float apz = pz0 - c3.z;
        float bpz = pz0 - c4.z;
        float d1 = abx * apx + aby * apy + abz * apz;    // ab.ap
        float d2 = acx * apx + acy * apy + acz * apz;    // ac.ap
        float h  = nx * apx + ny * apy + nz * apz;       // n.ap
        float vb = qac * d1 - qab * d2;
        float vc = qaa * d2 - qab * d1;
        const float iab = abz * dz;
        const float iac = acz * dz;
        const float ihz = nz * dz;

        // ---- ray crossing (den == nz), fully hoisted ----
        {
            float cpx2 = px - c5.x, cpy2 = py - c5.y;
            float e0 = c4.y - c5.y;                       // By - Cy
            float e1 = c5.x - c4.x;                       // Cx - Bx
            float un = e0 * cpx2 + e1 * cpy2;                          // u*den
            float vn = (c5.y - c3.y) * cpx2 + (c3.x - c5.x) * cpy2;    // v*den
            float wn = nz - un - vn;                                   // w*den
            bool c2d = (fabsf(nz) >= EPSF)
                     & (un * nz >= 0.0f) & (vn * nz >= 0.0f) & (wn * nz >= 0.0f);
            if (c2d) {
                float zhit = __fdividef(un * c3.z + vn * c4.z + wn * c5.z, nz);
                float fcnt = (zhit - pz0) * (float)G_DIM;
                int n = (int)ceilf(fminf(fmaxf(fcnt, 0.0f), (float)KPT));
                par ^= (1u << n) - 1u;
            }
        }

        #pragma unroll
        for (int k = 0; k < KPT; ++k) {
            // AB segment (FMUL.SAT clamp)
            float t1 = __saturatef(d1 * inv_ab);
            float rx = apx - t1 * abx;
            float ry = apy - t1 * aby;
            float rz = apz - t1 * abz;
            float dAB = rx * rx + ry * ry + rz * rz;
            // AC segment
            float t2 = __saturatef(d2 * inv_ac);
            rx = apx - t2 * acx;
            ry = apy - t2 * acy;
            rz = apz - t2 * acz;
            float dAC = rx * rx + ry * ry + rz * rz;
            // BC segment
            float d43 = (d2 - d1) + kbc;                  // bp.bc
            float t3 = __saturatef(d43 * inv_bc);
            rx = bpx - t3 * bcx;
            ry = bpy - t3 * bcy;
            rz = bpz - t3 * bcz;
            float dBC = rx * rx + ry * ry + rz * rz;

            float m = fminf(fminf(dAB, dAC), dBC);

            // interior: strict test (degenerate gram==0 excluded)
            float s = vb + vc;
            bool inter = (vb > 0.0f) & (vc > 0.0f) & (s < gram);
            float hh = h * h * inv_n2;
            m = inter ? hh : m;

            md[k] = fminf(md[k], m);

            // advance to next z point
            d1 += iab; d2 += iac; apz += dz; bpz += dz;
            h += ihz; vb += ivb; vc += ivc;
        }
    }

    const int pbase = ((ix * 32 + iy) * 32 + iz0);        // 16-aligned
    float* dst = g_md2s + chunk * N_PTS + pbase;
    #pragma unroll
    for (int q = 0; q < KPT / 4; ++q)
        *reinterpret_cast<float4*>(dst + 4 * q) =
            make_float4(md[4*q], md[4*q+1], md[4*q+2], md[4*q+3]);
    g_pars[chunk * N_GROUPS + g] = par;
}

__global__ void __launch_bounds__(256)
sdf_finalize(float* __restrict__ out)
{
    int p = blockIdx.x * 256 + threadIdx.x;               // [0, 32768)
    float m = INFINITY;
    unsigned par = 0u;
    #pragma unroll
    for (int c = 0; c < N_CHUNK; ++c) {
        m = fminf(m, g_md2s[c * N_PTS + p]);
        par ^= (g_pars[c * N_GROUPS + (p >> 4)] >> (p & 15));
    }
    out[p] = (par & 1u) ? sqrtf(m) : 0.0f;
}

extern "C" void kernel_launch(void* const* d_in, const int* in_sizes, int n_in,
                              void* d_out, int out_size)
{
    const int* faces = nullptr;
    const float* verts = nullptr;
    for (int i = 0; i < n_in; ++i) {
        if (in_sizes[i] == 3 * N_FACES)   faces = (const int*)d_in[i];
        else if (in_sizes[i] == 3 * 1026) verts = (const float*)d_in[i];
    }
    if (!faces) faces = (const int*)d_in[0];
    if (!verts) verts = (const float*)d_in[1];

    dim3 grid(N_GROUPS / 256, N_CHUNK);                   // 8 x 32 = 256 blocks
    sdf_main<<<grid, 256>>>(faces, verts);
    sdf_finalize<<<N_PTS / 256, 256>>>((float*)d_out);
}

// round 7
// speedup vs baseline: 4.7002x; 1.1591x over previous
#include <cuda_runtime.h>
#include <math.h>

// SDF2: mesh -> voxel (inside ? distance : 0) grid.
//   faces: int32 (1,2048,3), vertices: fp32 (1,1026,3), grid 32^3.
// Round-7 strategy:
//   - fma-pipe is the wall (rt=2 for 3-reg FFMA): minimize fma-pipe ops/k
//     (d43 loop-carried, h pre-scaled by 1/|n| so interior dist = hs*hs)
//   - perfect load balance: 592 blocks = 148 SMs x 4 (128 thr), 37 variable
//     chunks of 55-56 triangles, all blocks resident, equal work per SM
//   - reduction via RED atomics (atomicMin on float-as-uint, atomicXor parity)
//     + tiny init / finalize kernels (no multi-MB partial traffic)
//   - K=16 z-points/thread; d1,d2,d43,apz,bpz,hs,vb,vc incremental in z
//   - ray crossing hoisted per-triangle (den == nz), parity mask trick
//   - per-triangle constants precomputed once per block into smem.

#define G_DIM    32
#define N_PTS    (G_DIM * G_DIM * G_DIM)          // 32768
#define N_FACES  2048
#define N_CHUNKS 37
#define TRI_MAX  56
#define KPT      16
#define N_GROUPS (N_PTS / KPT)                    // 2048
#define THREADS  128
#define EPSF     1e-12f

__device__ unsigned g_md2min[N_PTS];              // float bits, monotone (md2 >= 0)
__device__ unsigned g_parity[N_GROUPS];           // 16 parity bits per word

__global__ void __launch_bounds__(256)
sdf_init()
{
    int i = blockIdx.x * 256 + threadIdx.x;
    if (i < N_PTS)    g_md2min[i] = 0x7F800000u;  // +inf
    if (i < N_GROUPS) g_parity[i] = 0u;
}

__global__ void __launch_bounds__(THREADS, 4)
sdf_main(const int* __restrict__ faces, const float* __restrict__ verts)
{
    // 8 float4 per triangle:
    // 0: ab.xyz, inv_ab   1: ac.xyz, inv_ac   2: bc.xyz, inv_bc
    // 3: A.xyz, kbc       4: B.xyz, inv_n     5: C.xyz, gram
    // 6: n.xyz, qab       7: qaa, qac, ivb, ivc
    __shared__ float4 tc[8 * TRI_MAX];            // 7.2 KB

    const int start = (blockIdx.y * N_FACES) / N_CHUNKS;
    const int end   = ((blockIdx.y + 1) * N_FACES) / N_CHUNKS;
    const int ntri  = end - start;

    // ---- staging: one thread per triangle computes all constants ----
    if (threadIdx.x < ntri) {
        const int f = threadIdx.x;
        const int base = (start + f) * 3;
        const float* va  = verts + 3 * faces[base + 0];
        const float* vbv = verts + 3 * faces[base + 1];
        const float* vcv = verts + 3 * faces[base + 2];
        float Ax = va[0],  Ay = va[1],  Az = va[2];
        float Bx = vbv[0], By = vbv[1], Bz = vbv[2];
        float Cx = vcv[0], Cy = vcv[1], Cz = vcv[2];

        float abx = Bx - Ax, aby = By - Ay, abz = Bz - Az;
        float acx = Cx - Ax, acy = Cy - Ay, acz = Cz - Az;
        float bcx = Cx - Bx, bcy = Cy - By, bcz = Cz - Bz;

        float qaa = abx * abx + aby * aby + abz * abz;
        float qab = abx * acx + aby * acy + abz * acz;
        float qac = acx * acx + acy * acy + acz * acz;
        float qbc = bcx * bcx + bcy * bcy + bcz * bcz;

        float nx = aby * acz - abz * acy;
        float ny = abz * acx - abx * acz;
        float nz = abx * acy - aby * acx;
        float gram = nx * nx + ny * ny + nz * nz;

        const float dzc = 1.0f / (float)G_DIM;
        float ivb = (qac * abz - qab * acz) * dzc;   // z-step of vb
        float ivc = (qaa * acz - qab * abz) * dzc;   // z-step of vc

        tc[8 * f + 0] = make_float4(abx, aby, abz, __fdividef(1.0f, fmaxf(qaa, EPSF)));
        tc[8 * f + 1] = make_float4(acx, acy, acz, __fdividef(1.0f, fmaxf(qac, EPSF)));
        tc[8 * f + 2] = make_float4(bcx, bcy, bcz, __fdividef(1.0f, fmaxf(qbc, EPSF)));
        tc[8 * f + 3] = make_float4(Ax, Ay, Az, qaa - qab);       // kbc
        tc[8 * f + 4] = make_float4(Bx, By, Bz, rsqrtf(fmaxf(gram, EPSF)));
        tc[8 * f + 5] = make_float4(Cx, Cy, Cz, gram);
        tc[8 * f + 6] = make_float4(nx, ny, nz, qab);
        tc[8 * f + 7] = make_float4(qaa, qac, ivb, ivc);
    }
    __syncthreads();

    const int g   = blockIdx.x * THREADS + threadIdx.x;   // [0, 2048)
    const int ix  = g >> 6;
    const int iy  = (g >> 1) & 31;
    const int iz0 = (g & 1) << 4;

    const float inv_g = 1.0f / (float)G_DIM;
    const float px  = ((float)ix  + 0.5f) * inv_g;
    const float py  = ((float)iy  + 0.5f) * inv_g;
    const float pz0 = ((float)iz0 + 0.5f) * inv_g;
    const float dz  = inv_g;

    float md[KPT];
    #pragma unroll
    for (int k = 0; k < KPT; ++k) md[k] = INFINITY;
    unsigned par = 0u;

    for (int f = 0; f < ntri; ++f) {
        const float4 c0 = tc[8 * f + 0];
        const float4 c1 = tc[8 * f + 1];
        const float4 c2 = tc[8 * f + 2];
        const float4 c3 = tc[8 * f + 3];
        const float4 c4 = tc[8 * f + 4];
        const float4 c5 = tc[8 * f + 5];
        const float4 c6 = tc[8 * f + 6];
        const float4 c7 = tc[8 * f + 7];
        const float abx = c0.x, aby = c0.y, abz = c0.z, inv_ab = c0.w;
        const float acx = c1.x, acy = c1.y, acz = c1.z, inv_ac = c1.w;
        const float bcx = c2.x, bcy = c2.y, bcz = c2.z, inv_bc = c2.w;
        const float kbc = c3.w, inv_n = c4.w, gram = c5.w;
        const float nx = c6.x, ny = c6.y, nz = c6.z, qab = c6.w;
        const float qaa = c7.x, qac = c7.y, ivb = c7.z, ivc = c7.w;

        // ---- per-thread init (z-invariant parts) ----
        const float apx = px - c3.x, apy = py - c3.y;
        const float bpx = px - c4.x, bpy = py - c4.y;
        float apz = pz0 - c3.z;
        float bpz = pz0 - c4.z;
        float d1 = abx * apx + aby * apy + abz * apz;     // ab.ap
        float d2 = acx * apx + acy * apy + acz * apz;     // ac.ap
        float d43 = (d2 - d1) + kbc;                      // bp.bc (affine in z)
        float hs = (nx * apx + ny * apy + nz * apz) * inv_n;  // (n.ap)/|n|
        float vb = qac * d1 - qab * d2;
        float vc = qaa * d2 - qab * d1;
        const float iab = abz * dz;
        const float iac = acz * dz;
        const float i43 = iac - iab;
        const float ihs = nz * dz * inv_n;

        // ---- ray crossing (den == nz), fully hoisted ----
        {
            float cpx2 = px - c5.x, cpy2 = py - c5.y;
            float e0 = c4.y - c5.y;                       // By - Cy
            float e1 = c5.x - c4.x;                       // Cx - Bx
            float un = e0 * cpx2 + e1 * cpy2;                          // u*den
            float vn = (c5.y - c3.y) * cpx2 + (c3.x - c5.x) * cpy2;    // v*den
            float wn = nz - un - vn;                                   // w*den
            bool c2d = (fabsf(nz) >= EPSF)
                     & (un * nz >= 0.0f) & (vn * nz >= 0.0f) & (wn * nz >= 0.0f);
            if (c2d) {
                float zhit = __fdividef(un * c3.z + vn * c4.z + wn * c5.z, nz);
                float fcnt = (zhit - pz0) * (float)G_DIM;
                int n = (int)ceilf(fminf(fmaxf(fcnt, 0.0f), (float)KPT));
                par ^= (1u << n) - 1u;
            }
        }

        #pragma unroll
        for (int k = 0; k < KPT; ++k) {
            // AB segment (FMUL.SAT clamp)
            float t1 = __saturatef(d1 * inv_ab);
            float rx = apx - t1 * abx;
            float ry = apy - t1 * aby;
            float rz = apz - t1 * abz;
            float dAB = rx * rx + ry * ry + rz * rz;
            // AC segment
            float t2 = __saturatef(d2 * inv_ac);
            rx = apx - t2 * acx;
            ry = apy - t2 * acy;
            rz = apz - t2 * acz;
            float dAC = rx * rx + ry * ry + rz * rz;
            // BC segment
            float t3 = __saturatef(d43 * inv_bc);
            rx = bpx - t3 * bcx;
            ry = bpy - t3 * bcy;
            rz = bpz - t3 * bcz;
            float dBC = rx * rx + ry * ry + rz * rz;

            float m = fminf(fminf(dAB, dAC), dBC);

            // interior: strict test (degenerate gram==0 excluded)
            float s = vb + vc;
            bool inter = (vb > 0.0f) & (vc > 0.0f) & (s < gram);
            float hh = hs * hs;
            m = inter ? hh : m;

            md[k] = fminf(md[k], m);

            // advance to next z point
            d1 += iab; d2 += iac; d43 += i43;
            apz += dz; bpz += dz;
            hs += ihs; vb += ivb; vc += ivc;
        }
    }

    // ---- reduce via RED atomics (no return value needed) ----
    const int pbase = ((ix * 32 + iy) * 32 + iz0);
    #pragma unroll
    for (int k = 0; k < KPT; ++k)
        atomicMin(&g_md2min[pbase + k], __float_as_uint(md[k]));
    if (par) atomicXor(&g_parity[g], par);
}

__global__ void __launch_bounds__(256)
sdf_finalize(float* __restrict__ out)
{
    int p = blockIdx.x * 256 + threadIdx.x;               // [0, 32768)
    float m = __uint_as_float(g_md2min[p]);
    unsigned par = (g_parity[p >> 4] >> (p & 15)) & 1u;
    out[p] = par ? sqrtf(m) : 0.0f;
}

extern "C" void kernel_launch(void* const* d_in, const int* in_sizes, int n_in,
                              void* d_out, int out_size)
{
    const int* faces = nullptr;
    const float* verts = nullptr;
    for (int i = 0; i < n_in; ++i) {
        if (in_sizes[i] == 3 * N_FACES)   faces = (const int*)d_in[i];
        else if (in_sizes[i] == 3 * 1026) verts = (const float*)d_in[i];
    }
    if (!faces) faces = (const int*)d_in[0];
    if (!verts) verts = (const float*)d_in[1];

    sdf_init<<<N_PTS / 256, 256>>>();
    dim3 grid(N_GROUPS / THREADS, N_CHUNKS);              // 16 x 37 = 592 blocks
    sdf_main<<<grid, THREADS>>>(faces, verts);
    sdf_finalize<<<N_PTS / 256, 256>>>((float*)d_out);
}